// round 10
// baseline (speedup 1.0000x reference)
#include <cuda_runtime.h>
#include <math.h>

// Problem constants
#define B_    32
#define C_    256
#define CR_   64
#define HW_   12544            // 112*112 floats per channel
#define NCH   (B_*C_)          // 8192 channels

// Phase geometry: 4 batches/phase = 51.4 MB slab (40% of 126 MB L2)
#define NBP   4
#define NPH   (B_/NBP)         // 8 phases
#define CHP   (NBP*C_)         // 1024 channels per phase

// v8 (32B) tiling: 12544/8 = 1568 = 6*256 + 32
#define NF8   6
#define NT8   32
// float4 tiling: 3136 = 12*256 + 64
#define NF4   12
#define NT4   64

__device__ float g_gap[NCH];
__device__ float g_gate[NCH];

struct F8 { float4 a, b; };

// 32-byte L2 evict-last load (sm_103 requires v8.b32 with L2:: modifiers)
__device__ __forceinline__ F8 ld_evict_last8(const float* p) {
    unsigned r0,r1,r2,r3,r4,r5,r6,r7;
    asm("ld.global.L2::evict_last.v8.b32 {%0,%1,%2,%3,%4,%5,%6,%7}, [%8];"
        : "=r"(r0),"=r"(r1),"=r"(r2),"=r"(r3),
          "=r"(r4),"=r"(r5),"=r"(r6),"=r"(r7) : "l"(p));
    F8 v;
    v.a.x = __uint_as_float(r0); v.a.y = __uint_as_float(r1);
    v.a.z = __uint_as_float(r2); v.a.w = __uint_as_float(r3);
    v.b.x = __uint_as_float(r4); v.b.y = __uint_as_float(r5);
    v.b.z = __uint_as_float(r6); v.b.w = __uint_as_float(r7);
    return v;
}

// ---------------------------------------------------------------------------
// Phase kernel 1: GAP for a 4-batch slab; pins slab in L2 (evict_last).
// One CTA per channel.
// ---------------------------------------------------------------------------
__global__ __launch_bounds__(256) void gap_phase(const float* __restrict__ x,
                                                 int ch0) {
    const int bc = ch0 + blockIdx.x;
    const int t  = threadIdx.x;
    const float* __restrict__ base = x + (size_t)bc * HW_;

    F8 v[NF8];
    #pragma unroll
    for (int k = 0; k < NF8; ++k)
        v[k] = ld_evict_last8(base + (t + k * 256) * 8);
    F8 vt;
    if (t < NT8) vt = ld_evict_last8(base + (t + NF8 * 256) * 8);

    float sum = 0.0f;
    #pragma unroll
    for (int k = 0; k < NF8; ++k)
        sum += ((v[k].a.x + v[k].a.y) + (v[k].a.z + v[k].a.w))
             + ((v[k].b.x + v[k].b.y) + (v[k].b.z + v[k].b.w));
    if (t < NT8)
        sum += ((vt.a.x + vt.a.y) + (vt.a.z + vt.a.w))
             + ((vt.b.x + vt.b.y) + (vt.b.z + vt.b.w));

    #pragma unroll
    for (int o = 16; o > 0; o >>= 1)
        sum += __shfl_xor_sync(0xFFFFFFFFu, sum, o);

    __shared__ float s[8];
    if ((t & 31) == 0) s[t >> 5] = sum;
    __syncthreads();
    if (t < 8) {
        sum = s[t];
        #pragma unroll
        for (int o = 4; o > 0; o >>= 1)
            sum += __shfl_xor_sync(0xFFu, sum, o);
        if (t == 0)
            g_gap[bc] = sum * (1.0f / (float)HW_);
    }
}

// ---------------------------------------------------------------------------
// Phase kernel 2: MLP + sigmoid for NBP batches. One CTA per batch.
// ---------------------------------------------------------------------------
__global__ __launch_bounds__(256) void fc_phase(
    const float* __restrict__ w1, const float* __restrict__ b1,
    const float* __restrict__ w2, const float* __restrict__ b2,
    int b0) {
    const int b = b0 + blockIdx.x;
    __shared__ float gap_s[C_];
    __shared__ float h_s[CR_];

    gap_s[threadIdx.x] = g_gap[b * C_ + threadIdx.x];
    __syncthreads();

    if (threadIdx.x < CR_) {
        float acc = b1[threadIdx.x];
        const float* __restrict__ w = w1 + threadIdx.x * C_;
        #pragma unroll 8
        for (int c = 0; c < C_; ++c) acc = fmaf(gap_s[c], w[c], acc);
        h_s[threadIdx.x] = fmaxf(acc, 0.0f);
    }
    __syncthreads();

    float acc = b2[threadIdx.x];
    const float* __restrict__ w = w2 + threadIdx.x * CR_;
    #pragma unroll 8
    for (int o = 0; o < CR_; ++o) acc = fmaf(h_s[o], w[o], acc);
    g_gate[b * C_ + threadIdx.x] = 1.0f / (1.0f + __expf(-acc));
}

// ---------------------------------------------------------------------------
// Phase kernel 3: out = x * gate for the pinned slab. Reads hit L2
// (__ldcs = hit-and-demote frees lines for the write stream); __stcs writes.
// ---------------------------------------------------------------------------
__global__ __launch_bounds__(256) void scale_phase(
    const float* __restrict__ x, float* __restrict__ out, int ch0) {
    const int bc = ch0 + blockIdx.x;
    const int t  = threadIdx.x;
    const float g = g_gate[bc];
    const float4* __restrict__ xp =
        reinterpret_cast<const float4*>(x + (size_t)bc * HW_);
    float4* __restrict__ op =
        reinterpret_cast<float4*>(out + (size_t)bc * HW_);

    float4 v[NF4];
    #pragma unroll
    for (int k = 0; k < NF4; ++k)
        v[k] = __ldcs(xp + t + k * 256);
    float4 vt;
    if (t < NT4) vt = __ldcs(xp + t + NF4 * 256);

    #pragma unroll
    for (int k = 0; k < NF4; ++k) {
        v[k].x *= g; v[k].y *= g; v[k].z *= g; v[k].w *= g;
        __stcs(op + t + k * 256, v[k]);
    }
    if (t < NT4) {
        vt.x *= g; vt.y *= g; vt.z *= g; vt.w *= g;
        __stcs(op + t + NF4 * 256, vt);
    }
}

// ---------------------------------------------------------------------------
// Launch: 8 phases x (gap -> fc -> scale). Kernel boundaries are barriers.
// ---------------------------------------------------------------------------
extern "C" void kernel_launch(void* const* d_in, const int* in_sizes, int n_in,
                              void* d_out, int out_size) {
    const float* x  = (const float*)d_in[0];
    const float* w1 = (const float*)d_in[1];
    const float* b1 = (const float*)d_in[2];
    const float* w2 = (const float*)d_in[3];
    const float* b2 = (const float*)d_in[4];
    float* out = (float*)d_out;

    for (int p = 0; p < NPH; ++p) {
        const int ch0 = p * CHP;
        const int b0  = p * NBP;
        gap_phase<<<CHP, 256>>>(x, ch0);
        fc_phase<<<NBP, 256>>>(w1, b1, w2, b2, b0);
        scale_phase<<<CHP, 256>>>(x, out, ch0);
    }
}

// round 11
// speedup vs baseline: 1.7561x; 1.7561x over previous
#include <cuda_runtime.h>
#include <math.h>

// Problem constants
#define B_    32
#define C_    256
#define CR_   64
#define HW_   12544       // 112*112 floats per channel
#define NCH   (B_*C_)     // 8192 channels
#define KEEP  2304        // tail channels pinned in L2 (~115.6 MB)

// v8 (32B) tiling: 12544/8 = 1568 = 6*256 + 32
#define NF8   6
#define NT8   32

__device__ float g_gap[NCH];
__device__ float g_gate[NCH];

struct F8 { float4 a, b; };

__device__ __forceinline__ F8 ld_evict_last8(const float* p) {
    unsigned r0,r1,r2,r3,r4,r5,r6,r7;
    asm("ld.global.L2::evict_last.v8.b32 {%0,%1,%2,%3,%4,%5,%6,%7}, [%8];"
        : "=r"(r0),"=r"(r1),"=r"(r2),"=r"(r3),
          "=r"(r4),"=r"(r5),"=r"(r6),"=r"(r7) : "l"(p));
    F8 v;
    v.a.x = __uint_as_float(r0); v.a.y = __uint_as_float(r1);
    v.a.z = __uint_as_float(r2); v.a.w = __uint_as_float(r3);
    v.b.x = __uint_as_float(r4); v.b.y = __uint_as_float(r5);
    v.b.z = __uint_as_float(r6); v.b.w = __uint_as_float(r7);
    return v;
}

__device__ __forceinline__ F8 ld_evict_first8(const float* p) {
    unsigned r0,r1,r2,r3,r4,r5,r6,r7;
    asm("ld.global.L2::evict_first.v8.b32 {%0,%1,%2,%3,%4,%5,%6,%7}, [%8];"
        : "=r"(r0),"=r"(r1),"=r"(r2),"=r"(r3),
          "=r"(r4),"=r"(r5),"=r"(r6),"=r"(r7) : "l"(p));
    F8 v;
    v.a.x = __uint_as_float(r0); v.a.y = __uint_as_float(r1);
    v.a.z = __uint_as_float(r2); v.a.w = __uint_as_float(r3);
    v.b.x = __uint_as_float(r4); v.b.y = __uint_as_float(r5);
    v.b.z = __uint_as_float(r6); v.b.w = __uint_as_float(r7);
    return v;
}

// 32B streaming store
__device__ __forceinline__ void st_cs8(float* p, const F8& v) {
    asm volatile("st.global.cs.v8.b32 [%0], {%1,%2,%3,%4,%5,%6,%7,%8};"
        :: "l"(p),
           "r"(__float_as_uint(v.a.x)), "r"(__float_as_uint(v.a.y)),
           "r"(__float_as_uint(v.a.z)), "r"(__float_as_uint(v.a.w)),
           "r"(__float_as_uint(v.b.x)), "r"(__float_as_uint(v.b.y)),
           "r"(__float_as_uint(v.b.z)), "r"(__float_as_uint(v.b.w))
        : "memory");
}

// ---------------------------------------------------------------------------
// Kernel 1: GAP. One CTA per channel; 32B loads; tail channels pinned in L2.
// ---------------------------------------------------------------------------
__global__ __launch_bounds__(256) void gap_kernel(const float* __restrict__ x) {
    const int bc = blockIdx.x;
    const int t  = threadIdx.x;
    const float* __restrict__ base = x + (size_t)bc * HW_;
    const bool keep = (bc >= NCH - KEEP);

    F8 v[NF8];
    F8 vt;
    if (keep) {
        #pragma unroll
        for (int k = 0; k < NF8; ++k)
            v[k] = ld_evict_last8(base + (t + k * 256) * 8);
        if (t < NT8) vt = ld_evict_last8(base + (t + NF8 * 256) * 8);
    } else {
        #pragma unroll
        for (int k = 0; k < NF8; ++k)
            v[k] = ld_evict_first8(base + (t + k * 256) * 8);
        if (t < NT8) vt = ld_evict_first8(base + (t + NF8 * 256) * 8);
    }

    float sum = 0.0f;
    #pragma unroll
    for (int k = 0; k < NF8; ++k)
        sum += ((v[k].a.x + v[k].a.y) + (v[k].a.z + v[k].a.w))
             + ((v[k].b.x + v[k].b.y) + (v[k].b.z + v[k].b.w));
    if (t < NT8)
        sum += ((vt.a.x + vt.a.y) + (vt.a.z + vt.a.w))
             + ((vt.b.x + vt.b.y) + (vt.b.z + vt.b.w));

    #pragma unroll
    for (int o = 16; o > 0; o >>= 1)
        sum += __shfl_xor_sync(0xFFFFFFFFu, sum, o);

    __shared__ float s[8];
    if ((t & 31) == 0) s[t >> 5] = sum;
    __syncthreads();
    if (t < 8) {
        sum = s[t];
        #pragma unroll
        for (int o = 4; o > 0; o >>= 1)
            sum += __shfl_xor_sync(0xFFu, sum, o);
        if (t == 0)
            g_gap[bc] = sum * (1.0f / (float)HW_);
    }
}

// ---------------------------------------------------------------------------
// Kernel 2: tiny 2-layer MLP + sigmoid gate. One CTA per batch sample.
// ---------------------------------------------------------------------------
__global__ __launch_bounds__(256) void se_fc_kernel(
    const float* __restrict__ w1, const float* __restrict__ b1,
    const float* __restrict__ w2, const float* __restrict__ b2) {
    const int b = blockIdx.x;
    __shared__ float gap_s[C_];
    __shared__ float h_s[CR_];

    gap_s[threadIdx.x] = g_gap[b * C_ + threadIdx.x];
    __syncthreads();

    if (threadIdx.x < CR_) {
        float acc = b1[threadIdx.x];
        const float* __restrict__ w = w1 + threadIdx.x * C_;
        #pragma unroll 8
        for (int c = 0; c < C_; ++c) acc = fmaf(gap_s[c], w[c], acc);
        h_s[threadIdx.x] = fmaxf(acc, 0.0f);
    }
    __syncthreads();

    float acc = b2[threadIdx.x];
    const float* __restrict__ w = w2 + threadIdx.x * CR_;
    #pragma unroll 8
    for (int o = 0; o < CR_; ++o) acc = fmaf(h_s[o], w[o], acc);
    g_gate[b * C_ + threadIdx.x] = 1.0f / (1.0f + __expf(-acc));
}

// ---------------------------------------------------------------------------
// Kernel 3: out = x * gate[bc]. One CTA per channel, reverse order (pinned
// tail first). 32B evict_first reads (demote-on-hit), 32B streaming stores.
// ---------------------------------------------------------------------------
__global__ __launch_bounds__(256) void scale_kernel(
    const float* __restrict__ x, float* __restrict__ out) {
    const int bc = NCH - 1 - (int)blockIdx.x;   // reverse order
    const int t  = threadIdx.x;
    const float g = g_gate[bc];
    const float* __restrict__ xp = x + (size_t)bc * HW_;
    float* __restrict__ op = out + (size_t)bc * HW_;

    F8 v[NF8];
    #pragma unroll
    for (int k = 0; k < NF8; ++k)
        v[k] = ld_evict_first8(xp + (t + k * 256) * 8);
    F8 vt;
    if (t < NT8) vt = ld_evict_first8(xp + (t + NF8 * 256) * 8);

    #pragma unroll
    for (int k = 0; k < NF8; ++k) {
        v[k].a.x *= g; v[k].a.y *= g; v[k].a.z *= g; v[k].a.w *= g;
        v[k].b.x *= g; v[k].b.y *= g; v[k].b.z *= g; v[k].b.w *= g;
        st_cs8(op + (t + k * 256) * 8, v[k]);
    }
    if (t < NT8) {
        vt.a.x *= g; vt.a.y *= g; vt.a.z *= g; vt.a.w *= g;
        vt.b.x *= g; vt.b.y *= g; vt.b.z *= g; vt.b.w *= g;
        st_cs8(op + (t + NF8 * 256) * 8, vt);
    }
}

// ---------------------------------------------------------------------------
extern "C" void kernel_launch(void* const* d_in, const int* in_sizes, int n_in,
                              void* d_out, int out_size) {
    const float* x  = (const float*)d_in[0];
    const float* w1 = (const float*)d_in[1];
    const float* b1 = (const float*)d_in[2];
    const float* w2 = (const float*)d_in[3];
    const float* b2 = (const float*)d_in[4];
    float* out = (float*)d_out;

    gap_kernel<<<NCH, 256>>>(x);
    se_fc_kernel<<<B_, 256>>>(w1, b1, w2, b2);
    scale_kernel<<<NCH, 256>>>(x, out);
}